// round 3
// baseline (speedup 1.0000x reference)
#include <cuda_runtime.h>
#include <cuda_fp16.h>
#include <cstdint>
#include <cstddef>

#define BATCH 32768
#define IN_F  512
#define OUT_F 512
#define DEG1  9
#define KDIM  4608             // IN_F * DEG1

#define BM 128
#define BN 256
#define BK 64
#define NSTAGE 4
#define NITER (KDIM / BK)      // 72
#define COEF_SCALE 4096.0f
#define OUT_SCALE  (1.0f / 4096.0f)

// 128B per k-row of a tile (64 fp16)
#define ASTAGE_BYTES (BM * 128)            // 16 KB
#define BSTAGE_BYTES (BN * 128)            // 32 KB
#define STAGE_BYTES  (ASTAGE_BYTES + BSTAGE_BYTES)
#define SMEM_TOTAL   (NSTAGE * STAGE_BYTES)  // 192 KB

// ---------------- scratch (__device__ globals; no allocations) ---------------
__device__ __align__(1024) __half g_A[(size_t)BATCH * KDIM];   // 288 MB
__device__ __align__(1024) __half g_B[(size_t)OUT_F * KDIM];   // 4.7 MB

// ---------------- helpers ----------------------------------------------------
__device__ __forceinline__ uint32_t smem_u32(const void* p) {
    uint32_t a;
    asm("{ .reg .u64 t; cvta.to.shared.u64 t, %1; cvt.u32.u64 %0, t; }" : "=r"(a) : "l"(p));
    return a;
}
__device__ __forceinline__ void cp_async16(uint32_t dst, const void* src) {
    asm volatile("cp.async.cg.shared.global [%0], [%1], 16;" :: "r"(dst), "l"(src) : "memory");
}
#define CP_COMMIT() asm volatile("cp.async.commit_group;" ::: "memory")
#define CP_WAIT(n)  asm volatile("cp.async.wait_group %0;" :: "n"(n) : "memory")

__device__ __forceinline__ void ldsm_x4(uint32_t f[4], uint32_t addr) {
    asm volatile("ldmatrix.sync.aligned.m8n8.x4.shared.b16 {%0,%1,%2,%3}, [%4];"
                 : "=r"(f[0]), "=r"(f[1]), "=r"(f[2]), "=r"(f[3]) : "r"(addr));
}
__device__ __forceinline__ void mma16816(float c[4], const uint32_t a[4],
                                         uint32_t b0, uint32_t b1) {
    asm volatile(
        "mma.sync.aligned.m16n8k16.row.col.f32.f16.f16.f32 "
        "{%0,%1,%2,%3}, {%4,%5,%6,%7}, {%8,%9}, {%0,%1,%2,%3};"
        : "+f"(c[0]), "+f"(c[1]), "+f"(c[2]), "+f"(c[3])
        : "r"(a[0]), "r"(a[1]), "r"(a[2]), "r"(a[3]), "r"(b0), "r"(b1));
}

// ---------------- kernel 1: A[b, d*512+i] = T_d(tanh(x[b,i])) fp16 -----------
__global__ void gen_a_kernel(const float* __restrict__ x, __half* __restrict__ A) {
    int b = blockIdx.x;
    int t = threadIdx.x;  // 0..255 -> i = 2t, 2t+1
    float2 xv = *reinterpret_cast<const float2*>(x + (size_t)b * IN_F + 2 * t);
    float ua = tanhf(xv.x);
    float ub = tanhf(xv.y);
    __half2* dst = reinterpret_cast<__half2*>(A + (size_t)b * KDIM + 2 * t);
    float pa = 1.0f, pb = 1.0f;
    float ca = ua,  cb = ub;
    dst[0] = __floats2half2_rn(1.0f, 1.0f);
    dst[IN_F / 2] = __floats2half2_rn(ua, ub);
#pragma unroll
    for (int d = 2; d <= 8; d++) {
        float na = 2.0f * ua * ca - pa;
        float nb = 2.0f * ub * cb - pb;
        dst[d * (IN_F / 2)] = __floats2half2_rn(na, nb);
        pa = ca; pb = cb; ca = na; cb = nb;
    }
}

// ---------------- kernel 2: B[o, d*512+i] = 4096 * C[i,o,d] fp16 -------------
__global__ void gen_b_kernel(const float* __restrict__ c, __half* __restrict__ B) {
    int o = blockIdx.x;
    int i = threadIdx.x;
    const float* src = c + ((size_t)i * OUT_F + o) * DEG1;
    __half* dst = B + (size_t)o * KDIM + i;
#pragma unroll
    for (int d = 0; d < DEG1; d++)
        dst[(size_t)d * IN_F] = __float2half_rn(src[d] * COEF_SCALE);
}

// ---------------- kernel 3: mma.sync GEMM  M=32768 N=512 K=4608 --------------
// BM=128 x BN=256 per CTA, BK=64, 4-stage cp.async pipeline, XOR-swizzled smem.
// 8 warps: wm = wid&3 (m stripes of 32), wn = wid>>2 (n stripes of 128).
__global__ __launch_bounds__(256, 1)
void gemm_kernel(const __half* __restrict__ A, const __half* __restrict__ B,
                 float* __restrict__ out) {
    extern __shared__ __align__(1024) char smem[];
    uint32_t sb = smem_u32(smem);
    int tid = threadIdx.x;
    int wid = tid >> 5, lid = tid & 31;
    int m0 = blockIdx.y * BM;
    int n0 = blockIdx.x * BN;
    int wm = wid & 3, wn = wid >> 1 >> 1;  // wn = wid >> 2

    float acc[2][16][4];
#pragma unroll
    for (int a = 0; a < 2; a++)
#pragma unroll
        for (int b = 0; b < 16; b++)
#pragma unroll
            for (int v = 0; v < 4; v++) acc[a][b][v] = 0.0f;

    // per-thread cp.async source/dest precomputation
    // A tile: 128 rows x 8 groups (16B); 1024 groups, 4 per thread
    // B tile: 256 rows x 8 groups; 2048 groups, 8 per thread
    int g_row = tid >> 3;          // 0..31
    int g_c   = tid & 7;           // 0..7

#define ISSUE_STAGE(it_)                                                          \
    do {                                                                          \
        int s_ = (it_) % NSTAGE;                                                  \
        uint32_t ab_ = sb + s_ * STAGE_BYTES;                                     \
        uint32_t bb_ = ab_ + ASTAGE_BYTES;                                        \
        int k0_ = (it_) * BK;                                                     \
        const char* agm_ = (const char*)(A + (size_t)m0 * KDIM + k0_);            \
        _Pragma("unroll")                                                         \
        for (int r_ = 0; r_ < 4; r_++) {                                          \
            int row_ = g_row + r_ * 32;                                           \
            uint32_t dst_ = ab_ + row_ * 128 + ((g_c ^ (row_ & 7)) << 4);         \
            cp_async16(dst_, agm_ + (size_t)row_ * (KDIM * 2) + g_c * 16);        \
        }                                                                         \
        const char* bgm_ = (const char*)(B + (size_t)n0 * KDIM + k0_);            \
        _Pragma("unroll")                                                         \
        for (int r_ = 0; r_ < 8; r_++) {                                          \
            int row_ = g_row + r_ * 32;                                           \
            uint32_t dst_ = bb_ + row_ * 128 + ((g_c ^ (row_ & 7)) << 4);         \
            cp_async16(dst_, bgm_ + (size_t)row_ * (KDIM * 2) + g_c * 16);        \
        }                                                                         \
    } while (0)

    // prefetch 3 stages
    ISSUE_STAGE(0); CP_COMMIT();
    ISSUE_STAGE(1); CP_COMMIT();
    ISSUE_STAGE(2); CP_COMMIT();

    // ldmatrix address components (same for every stage/ks modulo bases)
    int lr = lid & 7;        // row within 8x8 tile
    int lt = lid >> 3;       // tile index 0..3

    for (int it = 0; it < NITER; it++) {
        CP_WAIT(2);
        __syncthreads();
        if (it + 3 < NITER) { ISSUE_STAGE(it + 3); }
        CP_COMMIT();

        int s = it % NSTAGE;
        uint32_t abase = sb + s * STAGE_BYTES;
        uint32_t bbase = abase + ASTAGE_BYTES;

#pragma unroll
        for (int ks = 0; ks < 4; ks++) {
            // A fragments: 2 x (m16 k16)
            uint32_t afr[2][4];
#pragma unroll
            for (int mi = 0; mi < 2; mi++) {
                int m = wm * 32 + mi * 16 + (lt & 1) * 8 + lr;
                int g = ks * 2 + (lt >> 1);
                uint32_t addr = abase + m * 128 + ((g ^ (m & 7)) << 4);
                ldsm_x4(afr[mi], addr);
            }
            // B: 8 x ldmatrix.x4, each covers n16 x k16 (two n8 frags)
#pragma unroll
            for (int nb = 0; nb < 8; nb++) {
                uint32_t bfr[4];
                int n = wn * 128 + nb * 16 + (lt & 1) * 8 + lr;
                int g = ks * 2 + (lt >> 1);
                uint32_t addr = bbase + n * 128 + ((g ^ (n & 7)) << 4);
                ldsm_x4(bfr, addr);
#pragma unroll
                for (int h = 0; h < 2; h++) {
#pragma unroll
                    for (int mi = 0; mi < 2; mi++)
                        mma16816(acc[mi][2 * nb + h], afr[mi], bfr[h], bfr[h + 2]);
                }
            }
        }
        __syncthreads();
    }

    // ---------------- epilogue ----------------
    int mrow = lid >> 2;          // 0..7
    int ncol = (lid & 3) * 2;     // 0,2,4,6
#pragma unroll
    for (int mi = 0; mi < 2; mi++) {
#pragma unroll
        for (int ni = 0; ni < 16; ni++) {
            int n = n0 + wn * 128 + ni * 8 + ncol;
            int m_lo = m0 + wm * 32 + mi * 16 + mrow;
            float2 v0, v1;
            v0.x = acc[mi][ni][0] * OUT_SCALE;
            v0.y = acc[mi][ni][1] * OUT_SCALE;
            v1.x = acc[mi][ni][2] * OUT_SCALE;
            v1.y = acc[mi][ni][3] * OUT_SCALE;
            *reinterpret_cast<float2*>(out + (size_t)m_lo * OUT_F + n) = v0;
            *reinterpret_cast<float2*>(out + (size_t)(m_lo + 8) * OUT_F + n) = v1;
        }
    }
#undef ISSUE_STAGE
}

// ---------------- launch ------------------------------------------------------
extern "C" void kernel_launch(void* const* d_in, const int* in_sizes, int n_in,
                              void* d_out, int out_size) {
    const float* x     = (const float*)d_in[0];
    const float* coeff = (const float*)d_in[1];
    float* out = (float*)d_out;

    void* pA = nullptr;
    void* pB = nullptr;
    cudaGetSymbolAddress(&pA, g_A);
    cudaGetSymbolAddress(&pB, g_B);

    gen_a_kernel<<<BATCH, 256>>>(x, (__half*)pA);
    gen_b_kernel<<<OUT_F, IN_F>>>(coeff, (__half*)pB);

    static bool attr_set = false;
    if (!attr_set) {
        cudaFuncSetAttribute(gemm_kernel, cudaFuncAttributeMaxDynamicSharedMemorySize,
                             SMEM_TOTAL);
        attr_set = true;
    }
    dim3 grid(OUT_F / BN, BATCH / BM);   // (2, 256), n fastest for A L2 sharing
    gemm_kernel<<<grid, 256, SMEM_TOTAL>>>((const __half*)pA, (const __half*)pB, out);
}